// round 11
// baseline (speedup 1.0000x reference)
#include <cuda_runtime.h>
#include <math.h>

#define NMAX 32
#define BMAX 8
#define LEVELS 6

// SIZES computed in double then rounded to f32, matching numpy/jax promotion.
__constant__ float c_UPPER[LEVELS] = {
    (float)(2.23147392 * 22050.0 / 256.0),
    (float)(2.62519274 * 22050.0 / 256.0),
    (float)(3.74199546 * 22050.0 / 256.0),
    (float)(5.78800454 * 22050.0 / 256.0),
    (float)(8.02371882 * 22050.0 / 256.0),
    INFINITY
};
__constant__ float c_LOWER[LEVELS] = {
    0.0f,
    (float)(2.23147392 * 22050.0 / 256.0),
    (float)(2.62519274 * 22050.0 / 256.0),
    (float)(3.74199546 * 22050.0 / 256.0),
    (float)(5.78800454 * 22050.0 / 256.0),
    (float)(8.02371882 * 22050.0 / 256.0)
};

// ---------------------------------------------------------------------------
// ONE block per sample. 32 warps = 32 annotations (original index j = warp id).
// The reference's winner for an anchor = the cand annotation minimizing
// (length, original index) lexicographically (stable argsort by length +
// argmax-of-bool). Warp j contributes anchor a at level i iff cand(j,a,i) AND
// no k with (len_k,k) <lex (len_j,j) has cand(k,a,i). All cand tests are
// bit-identical to the reference arithmetic.
//
// No global accumulators, no atomics, no cross-block handshake: each block
// reduces in shared memory and writes out[b] directly. This minimizes the
// dependent global-memory chain (ann load -> reg load -> out store), which is
// what bounds this kernel at replay-time idle clocks.
// ---------------------------------------------------------------------------
__global__ __launch_bounds__(1024, 1)
void k_fused(const float* __restrict__ ann,
             const float* __restrict__ reg,
             float* __restrict__ out,
             int B, int L0, int A) {
    const int b    = blockIdx.x;
    const int tid  = threadIdx.x;
    const int j    = tid >> 5;          // warp id = annotation index
    const int lane = tid & 31;

    __shared__ float2 sh_se[NMAX];      // (start, end) per annotation
    __shared__ float  sh_len[NMAX];
    __shared__ float2 sh_part[NMAX];    // per-warp (lsum, lcnt) partials

    // --- load this sample's annotations into smem (coalesced-ish, 96 floats) ---
    if (tid < NMAX) {
        float s = ann[(b * NMAX + tid) * 3 + 0];
        float e = ann[(b * NMAX + tid) * 3 + 1];
        sh_se[tid]  = make_float2(s, e);
        sh_len[tid] = e - s;
    }
    __syncthreads();

    const float2 sej  = sh_se[j];
    const float  sj   = sej.x, ej = sej.y;
    const float  lenj = sh_len[j];
    // each lane caches annotation 'lane' for ballots (register, no re-LDS)
    const float2 se_l  = sh_se[lane];
    const float  len_l = sh_len[lane];
    const bool   lex_smaller = (len_l < lenj) || (len_l == lenj && lane < j);

    float lsum = 0.0f, lcnt = 0.0f;

    const float2* regb = (const float2*)reg + (size_t)b * A;

    int off = 0;  // pyramid row offset of current level
    #pragma unroll
    for (int lev = 0; lev < LEVELS; lev++) {
        const float lower = c_LOWER[lev];
        const float upper = c_UPPER[lev];
        const int   Li    = L0 >> lev;

        // m <= lenj exactly (monotone fp rounding): lenj < lower => no cand.
        if (lenj >= lower) {
            const float scale = (float)(1 << lev);
            const float inv   = 1.0f / scale;

            // conservative candidate anchor interval for (j, lev)
            float lo_pt = fmaxf(sj, ej - upper);   // e - inf -> s
            float hi_pt = fminf(ej, sj + upper);   // s + inf -> e
            int lo = (int)floorf(lo_pt * inv - 0.5f) - 2;
            int hi = (int)ceilf (hi_pt * inv - 0.5f) + 2;
            lo = lo < 0 ? 0 : lo;
            hi = hi > Li - 1 ? Li - 1 : hi;

            if (lo <= hi) {
                // possible-blocker mask (whole warp participates):
                // cand(k,·,lev) needs len_k >= lower (up to an ulp) and
                // m2 >= ~len_k/2 => len_k < ~2*upper. Conservative margins:
                // no true blocker is dropped; survivors get the exact test.
                const bool poss = lex_smaller && (len_l >= lower - 1.0f)
                                              && (len_l * 0.498f < upper);
                const unsigned bmask = __ballot_sync(0xFFFFFFFFu, poss);

                for (int a = lo + lane; a <= hi; a += 32) {
                    const float pt = ((float)a + 0.5f) * scale;
                    const float l  = pt - sj;
                    const float r  = ej - pt;
                    const float m  = fmaxf(l, r);
                    bool cand = (l >= 0.0f) & (r >= 0.0f) &
                                (m >= lower) & (m < upper);
                    if (!cand) continue;

                    // issue the regression load now; latency overlaps the scan
                    const float2 rb = __ldcg(&regb[off + a]);

                    // winner iff no possible blocker is actually cand here
                    bool first = true;
                    unsigned msk = bmask;
                    while (msk) {
                        const int k = __ffs(msk) - 1;
                        msk &= msk - 1;
                        const float2 se = sh_se[k];
                        const float l2 = pt - se.x;
                        const float r2 = se.y - pt;
                        const float m2 = fmaxf(l2, r2);
                        if ((l2 >= 0.0f) & (r2 >= 0.0f) &
                            (m2 >= lower) & (m2 < upper)) {
                            first = false;
                            break;
                        }
                    }
                    if (!first) continue;

                    const float nl = l * inv;
                    const float nr = r * inv;
                    const float a0 = pt - nl;
                    const float a1 = pt + nr;
                    const float b0 = rb.x, b1 = rb.y;

                    float inter = fminf(a1, b1) - fmaxf(a0, b0);
                    inter = fmaxf(inter, 0.0f);
                    const float uni = (a1 - a0) + (b1 - b0) - inter;
                    const float iou = __fdividef(inter, uni + 1e-7f);
                    const float enc = fmaxf(a1, b1) - fminf(a0, b0);
                    float giou = iou - __fdividef(enc - uni, enc + 1e-7f);
                    giou = fminf(fmaxf(giou, -1.0f), 1.0f);

                    lsum += 1.0f - giou;
                    lcnt += 1.0f;
                }
            }
        }
        off += Li;
    }

    // --- warp reduce -> smem partials -> warp 0 final reduce -> out[b] ---
    #pragma unroll
    for (int o = 16; o > 0; o >>= 1) {
        lsum += __shfl_down_sync(0xFFFFFFFFu, lsum, o);
        lcnt += __shfl_down_sync(0xFFFFFFFFu, lcnt, o);
    }
    if (lane == 0) sh_part[j] = make_float2(lsum, lcnt);
    __syncthreads();

    if (tid < 32) {
        float2 p = sh_part[tid];
        float s = p.x, c = p.y;
        #pragma unroll
        for (int o = 16; o > 0; o >>= 1) {
            s += __shfl_down_sync(0xFFFFFFFFu, s, o);
            c += __shfl_down_sync(0xFFFFFFFFu, c, o);
        }
        if (tid == 0) out[b] = __fdividef(s, fmaxf(c, 1.0f));
    }
}

// ---------------------------------------------------------------------------
// Launch. Inputs identified by element count (robust to metadata ordering):
//   regressions = max size; class_id = 1; anchors = power-of-two sizes (>1);
//   annotations = the remaining input. B = ann_size / 96.
// ---------------------------------------------------------------------------
extern "C" void kernel_launch(void* const* d_in, const int* in_sizes, int n_in,
                              void* d_out, int out_size) {
    int reg_i = -1;
    long reg_sz = -1;
    for (int i = 0; i < n_in; i++) {
        if ((long)in_sizes[i] > reg_sz) { reg_sz = in_sizes[i]; reg_i = i; }
    }
    int ann_i = -1;
    int L0 = 0;
    for (int i = 0; i < n_in; i++) {
        if (i == reg_i) continue;
        int s = in_sizes[i];
        if (s <= 1) continue;                 // class_id
        bool pow2 = (s & (s - 1)) == 0;
        if (pow2) { if (s > L0) L0 = s; }     // anchors; L0 = largest level
        else       { ann_i = i; }             // annotations (B*32*3, not pow2)
    }

    int B = in_sizes[ann_i] / (NMAX * 3);
    if (B > BMAX) B = BMAX;
    int A = (int)(reg_sz / (2 * B));

    const float* reg = (const float*)d_in[reg_i];
    const float* ann = (const float*)d_in[ann_i];
    float* out = (float*)d_out;

    k_fused<<<B, 1024>>>(ann, reg, out, B, L0, A);
}

// round 13
// speedup vs baseline: 1.4536x; 1.4536x over previous
#include <cuda_runtime.h>
#include <math.h>

#define NMAX 32
#define BMAX 8
#define LEVELS 6
// warp-arrivals per sample: NMAX*LEVELS blocks * 4 warps
#define ARRIVALS (NMAX * LEVELS * 4)

// SIZES computed in double then rounded to f32, matching numpy/jax promotion.
__constant__ float c_UPPER[LEVELS] = {
    (float)(2.23147392 * 22050.0 / 256.0),
    (float)(2.62519274 * 22050.0 / 256.0),
    (float)(3.74199546 * 22050.0 / 256.0),
    (float)(5.78800454 * 22050.0 / 256.0),
    (float)(8.02371882 * 22050.0 / 256.0),
    INFINITY
};
__constant__ float c_LOWER[LEVELS] = {
    0.0f,
    (float)(2.23147392 * 22050.0 / 256.0),
    (float)(2.62519274 * 22050.0 / 256.0),
    (float)(3.74199546 * 22050.0 / 256.0),
    (float)(5.78800454 * 22050.0 / 256.0),
    (float)(8.02371882 * 22050.0 / 256.0)
};

// Persistent accumulators. Zero at module load; the last warp per sample
// resets them, so every graph replay starts clean.
__device__ float    g_loss[BMAX];
__device__ float    g_cnt[BMAX];
__device__ unsigned g_counter[BMAX];

__device__ __forceinline__ float ld_l2(const float* p) {
    float v;
    asm volatile("ld.global.cg.f32 %0, [%1];" : "=f"(v) : "l"(p));
    return v;
}

// ---------------------------------------------------------------------------
// One block per (sample b, ORIGINAL annotation j, level lev); 128 threads.
// Warp-autonomous: no __syncthreads, no cross-warp smem reduction. Winner
// semantics identical to the reference: anchor a belongs to annotation j at
// level lev iff cand(j,a,lev) AND no k with (len_k,k) <lex (len_j,j) also has
// cand(k,a,lev). All cand tests bit-identical to the reference arithmetic;
// only provably-negative work is skipped.
//
// Finalize (PROVEN pattern, non-racy): each contributing warp atomically adds
// its partials; __threadfence; unconditional counter bump. The warp observing
// counter == ARRIVALS-1 knows every other warp's fenced adds are globally
// visible, so it READS the totals back through L2 (ld.cg), writes out[b], and
// resets the accumulators for the next graph replay.
// ---------------------------------------------------------------------------
__global__ __launch_bounds__(128, 1)
void k_fused(const float* __restrict__ ann,
             const float* __restrict__ reg,
             float* __restrict__ out,
             int B, int L0, int A) {
    const int bid  = blockIdx.x;
    const int b    = bid / (NMAX * LEVELS);
    const int rem  = bid % (NMAX * LEVELS);
    const int j    = rem / LEVELS;
    const int lev  = rem % LEVELS;
    const int tid  = threadIdx.x;
    const int lane = tid & 31;

    __shared__ float2 sh_se[NMAX];   // written redundantly by every warp

    // lane k of every warp loads annotation k (2 scalar LDG, L2-hot)
    const int abase = (b * NMAX + lane) * 3;
    const float s_l = ann[abase + 0];
    const float e_l = ann[abase + 1];
    const float len_l = e_l - s_l;

    // benign race: all warps store identical values; each warp only needs
    // its own writes ordered before its own reads -> __syncwarp suffices.
    sh_se[lane] = make_float2(s_l, e_l);
    __syncwarp();

    const float sj   = __shfl_sync(0xFFFFFFFFu, s_l, j);
    const float ej   = __shfl_sync(0xFFFFFFFFu, e_l, j);
    const float lenj = ej - sj;

    const float lower = c_LOWER[lev];
    const float upper = c_UPPER[lev];
    const float scale = (float)(1 << lev);
    const float inv   = 1.0f / scale;

    // possible-blocker mask: k must be lex-smaller and length-compatible with
    // this level band (conservative margins — no true blocker dropped;
    // survivors get the exact test).
    const bool lex  = (len_l < lenj) || (len_l == lenj && lane < j);
    const bool poss = lex && (len_l >= lower - 1.0f) && (len_l * 0.498f < upper);
    const unsigned bmask = __ballot_sync(0xFFFFFFFFu, poss);

    // conservative candidate anchor interval for (j, lev)
    int lo = 1, hi = 0;                     // empty
    if (lenj >= lower) {                    // m <= lenj exactly (monotone fp)
        float lo_pt = fmaxf(sj, ej - upper);   // e - inf -> s
        float hi_pt = fminf(ej, sj + upper);   // s + inf -> e
        int l = (int)floorf(lo_pt * inv - 0.5f) - 2;
        int h = (int)ceilf (hi_pt * inv - 0.5f) + 2;
        const int Li = L0 >> lev;
        l = l < 0 ? 0 : l;
        h = h > Li - 1 ? Li - 1 : h;
        if (l <= h) { lo = l; hi = h; }
    }

    // pyramid row offset of this level
    int off = 0;
    #pragma unroll
    for (int q = 0; q < LEVELS; q++) off += (q < lev) ? (L0 >> q) : 0;
    const float2* regb = (const float2*)reg + (size_t)b * A + off;

    float lsum = 0.0f;
    int   icnt = 0;

    // strip loop: a0 uniform across the block; per-lane validity predicate
    for (int a0 = lo; a0 <= hi; a0 += 128) {
        const int a = a0 + tid;
        bool contrib = false;

        const float pt = ((float)a + 0.5f) * scale;
        const float l  = pt - sj;
        const float r  = ej - pt;
        const float m  = fmaxf(l, r);
        const bool cand = (a <= hi) & (l >= 0.0f) & (r >= 0.0f) &
                          (m >= lower) & (m < upper);
        if (cand) {
            // issue the regression load now; latency overlaps the scan
            const float2 rb = __ldcg(&regb[a]);

            bool first = true;
            unsigned msk = bmask;
            while (msk) {
                const int k = __ffs(msk) - 1;
                msk &= msk - 1;
                const float2 se = sh_se[k];
                const float l2 = pt - se.x;
                const float r2 = se.y - pt;
                const float m2 = fmaxf(l2, r2);
                if ((l2 >= 0.0f) & (r2 >= 0.0f) &
                    (m2 >= lower) & (m2 < upper)) {
                    first = false;
                    break;
                }
            }

            if (first) {
                const float a0f = pt - l * inv;
                const float a1f = pt + r * inv;
                const float b0  = rb.x, b1 = rb.y;

                float inter = fminf(a1f, b1) - fmaxf(a0f, b0);
                inter = fmaxf(inter, 0.0f);
                const float uni = (a1f - a0f) + (b1 - b0) - inter;
                const float iou = __fdividef(inter, uni + 1e-7f);
                const float enc = fmaxf(a1f, b1) - fminf(a0f, b0);
                float giou = iou - __fdividef(enc - uni, enc + 1e-7f);
                giou = fminf(fmaxf(giou, -1.0f), 1.0f);

                lsum += 1.0f - giou;
                contrib = true;
            }
        }
        // warp count via ballot (uniform trip count -> legal)
        icnt += __popc(__ballot_sync(0xFFFFFFFFu, contrib));
    }

    // lsum warp reduce (icnt already warp-total, uniform)
    #pragma unroll
    for (int o = 16; o > 0; o >>= 1)
        lsum += __shfl_down_sync(0xFFFFFFFFu, lsum, o);

    if (lane == 0) {
        if (icnt > 0) {                       // sparse: most warps are empty
            atomicAdd(&g_loss[b], lsum);
            atomicAdd(&g_cnt[b], (float)icnt);
        }
        __threadfence();
        const unsigned v = atomicAdd(&g_counter[b], 1u);  // unconditional
        if (v == ARRIVALS - 1) {
            // counter == ARRIVALS-1 proves all other warps' fenced adds are
            // globally visible -> safe to READ totals back through L2.
            const float tot = ld_l2(&g_loss[b]);
            const float cnt = ld_l2(&g_cnt[b]);
            out[b] = __fdividef(tot, fmaxf(cnt, 1.0f));
            g_loss[b]    = 0.0f;     // reset for next replay
            g_cnt[b]     = 0.0f;
            g_counter[b] = 0u;
        }
    }
}

// ---------------------------------------------------------------------------
// Launch. Inputs identified by element count (robust to metadata ordering):
//   regressions = max size; class_id = 1; anchors = power-of-two sizes (>1);
//   annotations = the remaining input. B = ann_size / 96.
// ---------------------------------------------------------------------------
extern "C" void kernel_launch(void* const* d_in, const int* in_sizes, int n_in,
                              void* d_out, int out_size) {
    int reg_i = -1;
    long reg_sz = -1;
    for (int i = 0; i < n_in; i++) {
        if ((long)in_sizes[i] > reg_sz) { reg_sz = in_sizes[i]; reg_i = i; }
    }
    int ann_i = -1;
    int L0 = 0;
    for (int i = 0; i < n_in; i++) {
        if (i == reg_i) continue;
        int s = in_sizes[i];
        if (s <= 1) continue;                 // class_id
        bool pow2 = (s & (s - 1)) == 0;
        if (pow2) { if (s > L0) L0 = s; }     // anchors; L0 = largest level
        else       { ann_i = i; }             // annotations (B*32*3, not pow2)
    }

    int B = in_sizes[ann_i] / (NMAX * 3);
    if (B > BMAX) B = BMAX;
    int A = (int)(reg_sz / (2 * B));

    const float* reg = (const float*)d_in[reg_i];
    const float* ann = (const float*)d_in[ann_i];
    float* out = (float*)d_out;

    k_fused<<<B * NMAX * LEVELS, 128>>>(ann, reg, out, B, L0, A);
}